// round 6
// baseline (speedup 1.0000x reference)
#include <cuda_runtime.h>
#include <math.h>
#include <stdint.h>

#define TOK   65536      // B * NFEATS
#define BSAMP 2048
#define NF    32
#define DIMM  64
#define HEADS 8
#define DH    64
#define INNER 512
#define DROW  2048
#define DICOL 256
#define DIROW 1024
#define DEPTH 4
#define LN_EPS 1e-5f
#define KTILES (BSAMP / 64)   // 32 key tiles of 64 keys each — NOT 64!

// round fp32 -> tf32 (matches tensor-core operand quantization used by XLA/cuBLAS)
__device__ __forceinline__ float tf32(float x) {
    uint32_t u;
    asm("cvt.rna.tf32.f32 %0, %1;" : "=r"(u) : "f"(x));
    return __uint_as_float(u);
}

// ---------------- static scratch (no allocations allowed) ----------------
__device__ float g_x  [TOK * DIMM];          // activations [65536,64] == [2048,2048]
__device__ float g_xn [TOK * DIMM];          // normalized
__device__ float g_qkv[TOK * 3 * INNER];     // [65536,1536] (row path uses first 2048 rows)
__device__ float g_at [TOK * INNER];         // attention output [.,512]
__device__ float g_h  [TOK * 2 * DICOL];     // mlp hidden (col: [65536,512], row: [2048,2048])
__device__ float g_g  [TOK * DICOL];         // geglu out (col: [65536,256], row: [2048,1024])

// ---------------- concat x / x_cont -> [B, 32, 64] ----------------
__global__ void k_concat(const float* __restrict__ x, const float* __restrict__ xc,
                         float* __restrict__ out) {
    int i = blockIdx.x * 256 + threadIdx.x;
    if (i >= TOK * DIMM) return;
    int d = i & 63;
    int t = i >> 6;
    int f = t & 31;
    int s = t >> 5;
    float v = (f < 16) ? x[(s * 16 + f) * 64 + d] : xc[(s * 16 + (f - 16)) * 64 + d];
    out[i] = v;
}

// ---------------- LayerNorm width 64 (warp per row) ----------------
__global__ void k_ln64(const float* __restrict__ in, const float* __restrict__ g,
                       const float* __restrict__ b, float* __restrict__ out) {
    int warp = (blockIdx.x * blockDim.x + threadIdx.x) >> 5;
    int lane = threadIdx.x & 31;
    if (warp >= TOK) return;
    const float* r = in + warp * 64;
    float v0 = r[lane], v1 = r[lane + 32];
    float s = v0 + v1;
    #pragma unroll
    for (int o = 16; o; o >>= 1) s += __shfl_xor_sync(0xffffffffu, s, o);
    float m = s * (1.f / 64.f);
    float d0 = v0 - m, d1 = v1 - m;
    float q = d0 * d0 + d1 * d1;
    #pragma unroll
    for (int o = 16; o; o >>= 1) q += __shfl_xor_sync(0xffffffffu, q, o);
    float inv = rsqrtf(q * (1.f / 64.f) + LN_EPS);
    float* w = out + warp * 64;
    w[lane]      = d0 * inv * g[lane]      + b[lane];
    w[lane + 32] = d1 * inv * g[lane + 32] + b[lane + 32];
}

// ---------------- LayerNorm width 2048 (block per row) ----------------
__global__ void k_ln2048(const float* __restrict__ in, const float* __restrict__ g,
                         const float* __restrict__ b, float* __restrict__ out) {
    int row = blockIdx.x;
    const float* r = in + row * 2048;
    float local[8];
    float s = 0.f;
    #pragma unroll
    for (int i = 0; i < 8; i++) { local[i] = r[threadIdx.x + i * 256]; s += local[i]; }
    __shared__ float red[256];
    red[threadIdx.x] = s; __syncthreads();
    for (int o = 128; o; o >>= 1) { if (threadIdx.x < o) red[threadIdx.x] += red[threadIdx.x + o]; __syncthreads(); }
    float m = red[0] * (1.f / 2048.f);
    __syncthreads();
    float q = 0.f;
    #pragma unroll
    for (int i = 0; i < 8; i++) { float d = local[i] - m; q += d * d; }
    red[threadIdx.x] = q; __syncthreads();
    for (int o = 128; o; o >>= 1) { if (threadIdx.x < o) red[threadIdx.x] += red[threadIdx.x + o]; __syncthreads(); }
    float inv = rsqrtf(red[0] * (1.f / 2048.f) + LN_EPS);
    #pragma unroll
    for (int i = 0; i < 8; i++) {
        int c = threadIdx.x + i * 256;
        out[row * 2048 + c] = (local[i] - m) * inv * g[c] + b[c];
    }
}

// ---------------- tiled SGEMM (TF32-quantized operands): C = A@W (+bias)(+res) ----------------
// requires M%64==0, N%64==0, K%16==0 (true for all call sites)
__global__ void k_gemm(const float* __restrict__ A, const float* __restrict__ W,
                       const float* __restrict__ bias, const float* __restrict__ res,
                       float* __restrict__ C, int M, int N, int K) {
    __shared__ float As[16][64];
    __shared__ float Bs[16][64];
    int tid = threadIdx.x;
    int tx = tid & 15, ty = tid >> 4;
    int row0 = blockIdx.y * 64, col0 = blockIdx.x * 64;
    float acc[4][4] = {};
    for (int kt = 0; kt < K; kt += 16) {
        #pragma unroll
        for (int i = 0; i < 4; i++) {
            int idx = tid + i * 256;
            int r = idx >> 4, c = idx & 15;
            As[c][r] = tf32(A[(row0 + r) * K + kt + c]);
            int rb = idx >> 6, cb = idx & 63;
            Bs[rb][cb] = tf32(W[(kt + rb) * N + col0 + cb]);
        }
        __syncthreads();
        #pragma unroll
        for (int kk = 0; kk < 16; kk++) {
            float4 a  = *(const float4*)&As[kk][ty * 4];
            float4 bv = *(const float4*)&Bs[kk][tx * 4];
            float av[4] = {a.x, a.y, a.z, a.w};
            float bw[4] = {bv.x, bv.y, bv.z, bv.w};
            #pragma unroll
            for (int i = 0; i < 4; i++)
                #pragma unroll
                for (int j = 0; j < 4; j++)
                    acc[i][j] += av[i] * bw[j];
        }
        __syncthreads();
    }
    #pragma unroll
    for (int i = 0; i < 4; i++) {
        int r = row0 + ty * 4 + i;
        #pragma unroll
        for (int j = 0; j < 4; j++) {
            int c = col0 + tx * 4 + j;
            float v = acc[i][j];
            if (bias) v += bias[c];
            if (res)  v += res[r * N + c];
            C[r * N + c] = v;
        }
    }
}

// ---------------- col attention: CTA per (sample, head), full softmax 32x32 ----------------
__global__ void k_colattn(const float* __restrict__ qkv, float* __restrict__ out) {
    int s = blockIdx.x, h = blockIdx.y;
    __shared__ float q[32][64], k[32][65], v[32][64], p[32][32];
    int tid = threadIdx.x;
    #pragma unroll
    for (int i = 0; i < 8; i++) {
        int idx = tid + i * 256;
        int r = idx >> 6, d = idx & 63;
        int base = (s * 32 + r) * 1536 + h * 64 + d;
        q[r][d] = tf32(qkv[base]);
        k[r][d] = tf32(qkv[base + 512]);
        v[r][d] = tf32(qkv[base + 1024]);
    }
    __syncthreads();
    #pragma unroll
    for (int i = 0; i < 4; i++) {
        int idx = tid + i * 256;
        int r = idx >> 5, c = idx & 31;
        float acc = 0.f;
        #pragma unroll
        for (int d = 0; d < 64; d++) acc += q[r][d] * k[c][d];
        p[r][c] = acc * 0.125f;
    }
    __syncthreads();
    int lane = tid & 31, w = tid >> 5;
    #pragma unroll
    for (int rr = 0; rr < 4; rr++) {
        int r = w * 4 + rr;
        float x = p[r][lane];
        float mx = x;
        #pragma unroll
        for (int o = 16; o; o >>= 1) mx = fmaxf(mx, __shfl_xor_sync(0xffffffffu, mx, o));
        float e = expf(x - mx);
        float sm = e;
        #pragma unroll
        for (int o = 16; o; o >>= 1) sm += __shfl_xor_sync(0xffffffffu, sm, o);
        p[r][lane] = tf32(e / sm);     // ref rounds normalized softmax for the A@V einsum
    }
    __syncthreads();
    #pragma unroll
    for (int i = 0; i < 8; i++) {
        int idx = tid + i * 256;
        int r = idx >> 6, d = idx & 63;
        float acc = 0.f;
        #pragma unroll
        for (int j = 0; j < 32; j++) acc += p[r][j] * v[j][d];
        out[(s * 32 + r) * 512 + h * 64 + d] = acc;
    }
}

// ---------------- row attention: two-pass, CTA per (32-query tile, head) ----------------
// Sequence length = BSAMP = 2048 samples -> 32 tiles of 64 keys.
// Pass 1: global max m and denominator l per query.
// Pass 2: p = tf32(exp(s-m)/l) (matches ref's rounded softmax), accumulate P@V.
__global__ void k_rowattn(const float* __restrict__ qkv, float* __restrict__ out) {
    int qb = blockIdx.x, h = blockIdx.y;
    __shared__ float qs[32][65];
    __shared__ float ks[64][65];   // reused to hold p tile in pass 2
    __shared__ float vs[64][65];
    int tid = threadIdx.x;
    int row = tid >> 3;            // 0..31 query row
    int cg  = tid & 7;             // column group (8 cols each)
    #pragma unroll
    for (int i = 0; i < 8; i++) {
        int idx = tid + i * 256;
        int r = idx >> 6, d = idx & 63;
        qs[r][d] = tf32(qkv[(qb * 32 + r) * 1536 + h * 64 + d]);
    }
    __syncthreads();

    // ---------- pass 1: m, l ----------
    float m = -1e30f, l = 0.f;
    for (int kt = 0; kt < KTILES; kt++) {
        #pragma unroll
        for (int i = 0; i < 16; i++) {
            int idx = tid + i * 256;
            int r = idx >> 6, d = idx & 63;
            ks[r][d] = tf32(qkv[(kt * 64 + r) * 1536 + 512 + h * 64 + d]);
        }
        __syncthreads();
        float sv[8];
        float mx = m;
        #pragma unroll
        for (int jj = 0; jj < 8; jj++) {
            int j = cg * 8 + jj;
            float acc = 0.f;
            #pragma unroll
            for (int d = 0; d < 64; d++) acc += qs[row][d] * ks[j][d];
            acc *= 0.125f;
            sv[jj] = acc;
            mx = fmaxf(mx, acc);
        }
        #pragma unroll
        for (int o2 = 1; o2 < 8; o2 <<= 1) mx = fmaxf(mx, __shfl_xor_sync(0xffffffffu, mx, o2));
        float f = expf(m - mx);
        m = mx;
        float ps = 0.f;
        #pragma unroll
        for (int jj = 0; jj < 8; jj++) ps += expf(sv[jj] - mx);
        #pragma unroll
        for (int o2 = 1; o2 < 8; o2 <<= 1) ps += __shfl_xor_sync(0xffffffffu, ps, o2);
        l = l * f + ps;
        __syncthreads();               // before next tile overwrites ks
    }

    // ---------- pass 2: o = sum tf32(softmax) * v ----------
    float o[8] = {0, 0, 0, 0, 0, 0, 0, 0};
    for (int kt = 0; kt < KTILES; kt++) {
        #pragma unroll
        for (int i = 0; i < 16; i++) {
            int idx = tid + i * 256;
            int r = idx >> 6, d = idx & 63;
            int base = (kt * 64 + r) * 1536 + h * 64 + d;
            ks[r][d] = tf32(qkv[base + 512]);
            vs[r][d] = tf32(qkv[base + 1024]);
        }
        __syncthreads();
        float pv[8];
        #pragma unroll
        for (int jj = 0; jj < 8; jj++) {
            int j = cg * 8 + jj;
            float acc = 0.f;
            #pragma unroll
            for (int d = 0; d < 64; d++) acc += qs[row][d] * ks[j][d];
            acc *= 0.125f;
            pv[jj] = tf32(expf(acc - m) / l);
        }
        __syncthreads();               // score reads of ks finished
        #pragma unroll
        for (int jj = 0; jj < 8; jj++) ks[row][cg * 8 + jj] = pv[jj];  // p tile into ks
        __syncthreads();
        #pragma unroll
        for (int j = 0; j < 64; j++) {
            float pj = ks[row][j];
            #pragma unroll
            for (int dd = 0; dd < 8; dd++) o[dd] += pj * vs[j][cg * 8 + dd];
        }
        __syncthreads();               // before next tile overwrites ks/vs
    }
    #pragma unroll
    for (int dd = 0; dd < 8; dd++)
        out[(qb * 32 + row) * 512 + h * 64 + cg * 8 + dd] = o[dd];
}

// ---------------- GEGLU: out = a * gelu_exact(g) ----------------
__global__ void k_geglu(const float* __restrict__ h, float* __restrict__ out, int M, int F) {
    int i = blockIdx.x * 256 + threadIdx.x;
    if (i >= M * F) return;
    int r = i / F, c = i - r * F;
    float a = h[r * 2 * F + c];
    float g = h[r * 2 * F + F + c];
    out[i] = a * 0.5f * g * (1.f + erff(g * 0.70710678118654752f));
}

__global__ void k_copy(const float* __restrict__ in, float* __restrict__ out, int n) {
    int i = blockIdx.x * 256 + threadIdx.x;
    if (i < n) out[i] = in[i];
}

// ---------------- driver ----------------
extern "C" void kernel_launch(void* const* d_in, const int* in_sizes, int n_in,
                              void* d_out, int out_size) {
    const float* x       = (const float*)d_in[0];
    const float* x_cont  = (const float*)d_in[1];
    const float* c_ln1_g = (const float*)d_in[2];
    const float* c_ln1_b = (const float*)d_in[3];
    const float* c_wqkv  = (const float*)d_in[4];
    const float* c_wo_w  = (const float*)d_in[5];
    const float* c_wo_b  = (const float*)d_in[6];
    const float* c_ln2_g = (const float*)d_in[7];
    const float* c_ln2_b = (const float*)d_in[8];
    const float* c_w1    = (const float*)d_in[9];
    const float* c_b1    = (const float*)d_in[10];
    const float* c_w2    = (const float*)d_in[11];
    const float* c_b2    = (const float*)d_in[12];
    const float* r_ln1_g = (const float*)d_in[13];
    const float* r_ln1_b = (const float*)d_in[14];
    const float* r_wqkv  = (const float*)d_in[15];
    const float* r_wo_w  = (const float*)d_in[16];
    const float* r_wo_b  = (const float*)d_in[17];
    const float* r_ln2_g = (const float*)d_in[18];
    const float* r_ln2_b = (const float*)d_in[19];
    const float* r_w1    = (const float*)d_in[20];
    const float* r_b1    = (const float*)d_in[21];
    const float* r_w2    = (const float*)d_in[22];
    const float* r_b2    = (const float*)d_in[23];

    float *px, *pxn, *pqkv, *pat, *ph, *pg;
    cudaGetSymbolAddress((void**)&px,   g_x);
    cudaGetSymbolAddress((void**)&pxn,  g_xn);
    cudaGetSymbolAddress((void**)&pqkv, g_qkv);
    cudaGetSymbolAddress((void**)&pat,  g_at);
    cudaGetSymbolAddress((void**)&ph,   g_h);
    cudaGetSymbolAddress((void**)&pg,   g_g);

    k_concat<<<(TOK * DIMM) / 256, 256>>>(x, x_cont, px);

    for (int L = 0; L < DEPTH; L++) {
        // ----- col block -----
        k_ln64<<<TOK / 8, 256>>>(px, c_ln1_g + L * 64, c_ln1_b + L * 64, pxn);
        k_gemm<<<dim3(1536 / 64, TOK / 64), 256>>>(pxn, c_wqkv + L * 64 * 1536,
                                                   nullptr, nullptr, pqkv, TOK, 1536, 64);
        k_colattn<<<dim3(BSAMP, HEADS), 256>>>(pqkv, pat);
        k_gemm<<<dim3(1, TOK / 64), 256>>>(pat, c_wo_w + L * 512 * 64,
                                           c_wo_b + L * 64, pxn, px, TOK, 64, 512);
        k_ln64<<<TOK / 8, 256>>>(px, c_ln2_g + L * 64, c_ln2_b + L * 64, pxn);
        k_gemm<<<dim3(512 / 64, TOK / 64), 256>>>(pxn, c_w1 + L * 64 * 512,
                                                  c_b1 + L * 512, nullptr, ph, TOK, 512, 64);
        k_geglu<<<(TOK * DICOL) / 256, 256>>>(ph, pg, TOK, DICOL);
        k_gemm<<<dim3(1, TOK / 64), 256>>>(pg, c_w2 + L * 256 * 64,
                                           c_b2 + L * 64, pxn, px, TOK, 64, 256);

        // ----- row block (x viewed as [2048, 2048], identical memory layout) -----
        k_ln2048<<<BSAMP, 256>>>(px, r_ln1_g + L * 2048, r_ln1_b + L * 2048, pxn);
        k_gemm<<<dim3(1536 / 64, BSAMP / 64), 256>>>(pxn, r_wqkv + (size_t)L * 2048 * 1536,
                                                     nullptr, nullptr, pqkv, BSAMP, 1536, 2048);
        k_rowattn<<<dim3(BSAMP / 32, HEADS), 256>>>(pqkv, pat);
        k_gemm<<<dim3(2048 / 64, BSAMP / 64), 256>>>(pat, r_wo_w + (size_t)L * 512 * 2048,
                                                     r_wo_b + L * 2048, pxn, px, BSAMP, 2048, 512);
        k_ln2048<<<BSAMP, 256>>>(px, r_ln2_g + L * 2048, r_ln2_b + L * 2048, pxn);
        k_gemm<<<dim3(2048 / 64, BSAMP / 64), 256>>>(pxn, r_w1 + (size_t)L * 2048 * 2048,
                                                     r_b1 + L * 2048, nullptr, ph, BSAMP, 2048, 2048);
        k_geglu<<<(BSAMP * DIROW) / 256, 256>>>(ph, pg, BSAMP, DIROW);
        k_gemm<<<dim3(2048 / 64, BSAMP / 64), 256>>>(pg, r_w2 + (size_t)L * 1024 * 2048,
                                                     r_b2 + L * 2048, pxn, px, BSAMP, 2048, 1024);
    }

    k_copy<<<(TOK * DIMM) / 256, 256>>>(px, (float*)d_out, TOK * DIMM);
}

// round 7
// speedup vs baseline: 1.6370x; 1.6370x over previous
#include <cuda_runtime.h>
#include <math.h>
#include <stdint.h>

#define TOK   65536      // B * NFEATS
#define BSAMP 2048
#define NF    32
#define DIMM  64
#define HEADS 8
#define DH    64
#define INNER 512
#define DROW  2048
#define DICOL 256
#define DIROW 1024
#define DEPTH 4
#define LN_EPS 1e-5f
#define KTILES (BSAMP / 64)   // 32 key tiles of 64 keys each

// round fp32 -> tf32 (matches tensor-core operand quantization)
__device__ __forceinline__ float tf32(float x) {
    uint32_t u;
    asm("cvt.rna.tf32.f32 %0, %1;" : "=r"(u) : "f"(x));
    return __uint_as_float(u);
}

// m16n8k8 TF32 tensor-core mma (A row-major, B col-major, fp32 accum)
__device__ __forceinline__ void mma_tf32(float* c, const uint32_t* a, const uint32_t* b) {
    asm volatile(
        "mma.sync.aligned.m16n8k8.row.col.f32.tf32.tf32.f32 "
        "{%0,%1,%2,%3}, {%4,%5,%6,%7}, {%8,%9}, {%0,%1,%2,%3};"
        : "+f"(c[0]), "+f"(c[1]), "+f"(c[2]), "+f"(c[3])
        : "r"(a[0]), "r"(a[1]), "r"(a[2]), "r"(a[3]), "r"(b[0]), "r"(b[1]));
}

// ---------------- static scratch (no allocations allowed) ----------------
__device__ float g_x  [TOK * DIMM];          // activations [65536,64] == [2048,2048]
__device__ float g_xn [TOK * DIMM];          // normalized
__device__ float g_qkv[TOK * 3 * INNER];     // [65536,1536] (row path uses first 2048 rows)
__device__ float g_at [TOK * INNER];         // attention output [.,512]
__device__ float g_h  [TOK * 2 * DICOL];     // mlp hidden (col: [65536,512], row: [2048,2048])
__device__ float g_g  [TOK * DICOL];         // geglu out (col: [65536,256], row: [2048,1024])

// ---------------- concat x / x_cont -> [B, 32, 64] ----------------
__global__ void k_concat(const float* __restrict__ x, const float* __restrict__ xc,
                         float* __restrict__ out) {
    int i = blockIdx.x * 256 + threadIdx.x;
    if (i >= TOK * DIMM) return;
    int d = i & 63;
    int t = i >> 6;
    int f = t & 31;
    int s = t >> 5;
    float v = (f < 16) ? x[(s * 16 + f) * 64 + d] : xc[(s * 16 + (f - 16)) * 64 + d];
    out[i] = v;
}

// ---------------- LayerNorm width 64 (warp per row) ----------------
__global__ void k_ln64(const float* __restrict__ in, const float* __restrict__ g,
                       const float* __restrict__ b, float* __restrict__ out) {
    int warp = (blockIdx.x * blockDim.x + threadIdx.x) >> 5;
    int lane = threadIdx.x & 31;
    if (warp >= TOK) return;
    const float* r = in + warp * 64;
    float v0 = r[lane], v1 = r[lane + 32];
    float s = v0 + v1;
    #pragma unroll
    for (int o = 16; o; o >>= 1) s += __shfl_xor_sync(0xffffffffu, s, o);
    float m = s * (1.f / 64.f);
    float d0 = v0 - m, d1 = v1 - m;
    float q = d0 * d0 + d1 * d1;
    #pragma unroll
    for (int o = 16; o; o >>= 1) q += __shfl_xor_sync(0xffffffffu, q, o);
    float inv = rsqrtf(q * (1.f / 64.f) + LN_EPS);
    float* w = out + warp * 64;
    w[lane]      = d0 * inv * g[lane]      + b[lane];
    w[lane + 32] = d1 * inv * g[lane + 32] + b[lane + 32];
}

// ---------------- LayerNorm width 2048 (block per row) ----------------
__global__ void k_ln2048(const float* __restrict__ in, const float* __restrict__ g,
                         const float* __restrict__ b, float* __restrict__ out) {
    int row = blockIdx.x;
    const float* r = in + row * 2048;
    float local[8];
    float s = 0.f;
    #pragma unroll
    for (int i = 0; i < 8; i++) { local[i] = r[threadIdx.x + i * 256]; s += local[i]; }
    __shared__ float red[256];
    red[threadIdx.x] = s; __syncthreads();
    for (int o = 128; o; o >>= 1) { if (threadIdx.x < o) red[threadIdx.x] += red[threadIdx.x + o]; __syncthreads(); }
    float m = red[0] * (1.f / 2048.f);
    __syncthreads();
    float q = 0.f;
    #pragma unroll
    for (int i = 0; i < 8; i++) { float d = local[i] - m; q += d * d; }
    red[threadIdx.x] = q; __syncthreads();
    for (int o = 128; o; o >>= 1) { if (threadIdx.x < o) red[threadIdx.x] += red[threadIdx.x + o]; __syncthreads(); }
    float inv = rsqrtf(red[0] * (1.f / 2048.f) + LN_EPS);
    #pragma unroll
    for (int i = 0; i < 8; i++) {
        int c = threadIdx.x + i * 256;
        out[row * 2048 + c] = (local[i] - m) * inv * g[c] + b[c];
    }
}

// ---------------- tensor-core TF32 GEMM: C = A[M,K] @ W[K,N] (+bias)(+res) ----------------
// BM=128, BK=16, 256 threads, 8 warps. BN in {128, 64}.
// requires M%128==0, N%BN==0, K%16==0 (true for all call sites)
template<int BN>
__global__ void __launch_bounds__(256)
k_gemm_mma(const float* __restrict__ A, const float* __restrict__ W,
           const float* __restrict__ bias, const float* __restrict__ res,
           float* __restrict__ C, int M, int N, int K) {
    constexpr int BM = 128, BK = 16;
    constexpr int WN = 32;
    constexpr int WM = (BN == 128) ? 64 : 32;
    constexpr int WARPS_N = BN / WN;           // 4 or 2
    constexpr int MT = WM / 16;                // 4 or 2
    constexpr int NT = WN / 8;                 // 4
    // +8-word pad: stride%32==8 -> fragment loads conflict-free (bank = 8*tg + gid)
    __shared__ float As[BK][BM + 8];
    __shared__ float Bs[BK][BN + 8];

    int tid  = threadIdx.x;
    int warp = tid >> 5, lane = tid & 31;
    int gid  = lane >> 2, tg = lane & 3;
    int wm   = warp / WARPS_N, wn = warp % WARPS_N;
    int row0 = blockIdx.y * BM, col0 = blockIdx.x * BN;

    float acc[MT][NT][4];
    #pragma unroll
    for (int i = 0; i < MT; i++)
        #pragma unroll
        for (int j = 0; j < NT; j++)
            #pragma unroll
            for (int q = 0; q < 4; q++) acc[i][j][q] = 0.f;

    for (int kt = 0; kt < K; kt += BK) {
        #pragma unroll
        for (int i = 0; i < (BM * BK) / 256; i++) {
            int li = tid + i * 256;
            int m = li >> 4, k = li & 15;
            As[k][m] = tf32(A[(size_t)(row0 + m) * K + kt + k]);
        }
        #pragma unroll
        for (int i = 0; i < (BK * BN) / 256; i++) {
            int li = tid + i * 256;
            int k = li / BN, n = li % BN;
            Bs[k][n] = tf32(W[(size_t)(kt + k) * N + col0 + n]);
        }
        __syncthreads();
        #pragma unroll
        for (int ks = 0; ks < BK; ks += 8) {
            uint32_t af[MT][4], bf[NT][2];
            #pragma unroll
            for (int mt = 0; mt < MT; mt++) {
                int m0 = wm * WM + mt * 16;
                af[mt][0] = __float_as_uint(As[ks + tg    ][m0 + gid    ]);
                af[mt][1] = __float_as_uint(As[ks + tg    ][m0 + gid + 8]);
                af[mt][2] = __float_as_uint(As[ks + tg + 4][m0 + gid    ]);
                af[mt][3] = __float_as_uint(As[ks + tg + 4][m0 + gid + 8]);
            }
            #pragma unroll
            for (int nt = 0; nt < NT; nt++) {
                int n0 = wn * WN + nt * 8 + gid;
                bf[nt][0] = __float_as_uint(Bs[ks + tg    ][n0]);
                bf[nt][1] = __float_as_uint(Bs[ks + tg + 4][n0]);
            }
            #pragma unroll
            for (int mt = 0; mt < MT; mt++)
                #pragma unroll
                for (int nt = 0; nt < NT; nt++)
                    mma_tf32(acc[mt][nt], af[mt], bf[nt]);
        }
        __syncthreads();
    }

    #pragma unroll
    for (int mt = 0; mt < MT; mt++) {
        #pragma unroll
        for (int nt = 0; nt < NT; nt++) {
            int r0 = row0 + wm * WM + mt * 16 + gid;
            int c  = col0 + wn * WN + nt * 8 + tg * 2;
            float v0 = acc[mt][nt][0], v1 = acc[mt][nt][1];
            float v2 = acc[mt][nt][2], v3 = acc[mt][nt][3];
            if (bias) {
                float b0 = bias[c], b1 = bias[c + 1];
                v0 += b0; v1 += b1; v2 += b0; v3 += b1;
            }
            if (res) {
                v0 += res[(size_t)r0 * N + c];
                v1 += res[(size_t)r0 * N + c + 1];
                v2 += res[(size_t)(r0 + 8) * N + c];
                v3 += res[(size_t)(r0 + 8) * N + c + 1];
            }
            C[(size_t)r0 * N + c]           = v0;
            C[(size_t)r0 * N + c + 1]       = v1;
            C[(size_t)(r0 + 8) * N + c]     = v2;
            C[(size_t)(r0 + 8) * N + c + 1] = v3;
        }
    }
}

// ---------------- col attention: CTA per (sample, head), full softmax 32x32 ----------------
__global__ void k_colattn(const float* __restrict__ qkv, float* __restrict__ out) {
    int s = blockIdx.x, h = blockIdx.y;
    __shared__ float q[32][64], k[32][65], v[32][64], p[32][32];
    int tid = threadIdx.x;
    #pragma unroll
    for (int i = 0; i < 8; i++) {
        int idx = tid + i * 256;
        int r = idx >> 6, d = idx & 63;
        int base = (s * 32 + r) * 1536 + h * 64 + d;
        q[r][d] = tf32(qkv[base]);
        k[r][d] = tf32(qkv[base + 512]);
        v[r][d] = tf32(qkv[base + 1024]);
    }
    __syncthreads();
    #pragma unroll
    for (int i = 0; i < 4; i++) {
        int idx = tid + i * 256;
        int r = idx >> 5, c = idx & 31;
        float acc = 0.f;
        #pragma unroll
        for (int d = 0; d < 64; d++) acc += q[r][d] * k[c][d];
        p[r][c] = acc * 0.125f;
    }
    __syncthreads();
    int lane = tid & 31, w = tid >> 5;
    #pragma unroll
    for (int rr = 0; rr < 4; rr++) {
        int r = w * 4 + rr;
        float x = p[r][lane];
        float mx = x;
        #pragma unroll
        for (int o = 16; o; o >>= 1) mx = fmaxf(mx, __shfl_xor_sync(0xffffffffu, mx, o));
        float e = expf(x - mx);
        float sm = e;
        #pragma unroll
        for (int o = 16; o; o >>= 1) sm += __shfl_xor_sync(0xffffffffu, sm, o);
        p[r][lane] = tf32(e / sm);
    }
    __syncthreads();
    #pragma unroll
    for (int i = 0; i < 8; i++) {
        int idx = tid + i * 256;
        int r = idx >> 6, d = idx & 63;
        float acc = 0.f;
        #pragma unroll
        for (int j = 0; j < 32; j++) acc += p[r][j] * v[j][d];
        out[(s * 32 + r) * 512 + h * 64 + d] = acc;
    }
}

// ---------------- row attention: two-pass, CTA per (32-query tile, head) ----------------
__global__ void k_rowattn(const float* __restrict__ qkv, float* __restrict__ out) {
    int qb = blockIdx.x, h = blockIdx.y;
    __shared__ float qs[32][65];
    __shared__ float ks[64][65];   // reused to hold p tile in pass 2
    __shared__ float vs[64][65];
    int tid = threadIdx.x;
    int row = tid >> 3;            // 0..31 query row
    int cg  = tid & 7;             // column group (8 cols each)
    #pragma unroll
    for (int i = 0; i < 8; i++) {
        int idx = tid + i * 256;
        int r = idx >> 6, d = idx & 63;
        qs[r][d] = tf32(qkv[(qb * 32 + r) * 1536 + h * 64 + d]);
    }
    __syncthreads();

    // ---------- pass 1: m, l ----------
    float m = -1e30f, l = 0.f;
    for (int kt = 0; kt < KTILES; kt++) {
        #pragma unroll
        for (int i = 0; i < 16; i++) {
            int idx = tid + i * 256;
            int r = idx >> 6, d = idx & 63;
            ks[r][d] = tf32(qkv[(kt * 64 + r) * 1536 + 512 + h * 64 + d]);
        }
        __syncthreads();
        float sv[8];
        float mx = m;
        #pragma unroll
        for (int jj = 0; jj < 8; jj++) {
            int j = cg * 8 + jj;
            float acc = 0.f;
            #pragma unroll
            for (int d = 0; d < 64; d++) acc += qs[row][d] * ks[j][d];
            acc *= 0.125f;
            sv[jj] = acc;
            mx = fmaxf(mx, acc);
        }
        #pragma unroll
        for (int o2 = 1; o2 < 8; o2 <<= 1) mx = fmaxf(mx, __shfl_xor_sync(0xffffffffu, mx, o2));
        float f = expf(m - mx);
        m = mx;
        float ps = 0.f;
        #pragma unroll
        for (int jj = 0; jj < 8; jj++) ps += expf(sv[jj] - mx);
        #pragma unroll
        for (int o2 = 1; o2 < 8; o2 <<= 1) ps += __shfl_xor_sync(0xffffffffu, ps, o2);
        l = l * f + ps;
        __syncthreads();               // before next tile overwrites ks
    }

    // ---------- pass 2: o = sum tf32(softmax) * v ----------
    float o[8] = {0, 0, 0, 0, 0, 0, 0, 0};
    for (int kt = 0; kt < KTILES; kt++) {
        #pragma unroll
        for (int i = 0; i < 16; i++) {
            int idx = tid + i * 256;
            int r = idx >> 6, d = idx & 63;
            int base = (kt * 64 + r) * 1536 + h * 64 + d;
            ks[r][d] = tf32(qkv[base + 512]);
            vs[r][d] = tf32(qkv[base + 1024]);
        }
        __syncthreads();
        float pv[8];
        #pragma unroll
        for (int jj = 0; jj < 8; jj++) {
            int j = cg * 8 + jj;
            float acc = 0.f;
            #pragma unroll
            for (int d = 0; d < 64; d++) acc += qs[row][d] * ks[j][d];
            acc *= 0.125f;
            pv[jj] = tf32(expf(acc - m) / l);
        }
        __syncthreads();               // score reads of ks finished
        #pragma unroll
        for (int jj = 0; jj < 8; jj++) ks[row][cg * 8 + jj] = pv[jj];  // p tile into ks
        __syncthreads();
        #pragma unroll
        for (int j = 0; j < 64; j++) {
            float pj = ks[row][j];
            #pragma unroll
            for (int dd = 0; dd < 8; dd++) o[dd] += pj * vs[j][cg * 8 + dd];
        }
        __syncthreads();               // before next tile overwrites ks/vs
    }
    #pragma unroll
    for (int dd = 0; dd < 8; dd++)
        out[(qb * 32 + row) * 512 + h * 64 + cg * 8 + dd] = o[dd];
}

// ---------------- GEGLU: out = a * gelu_exact(g) ----------------
__global__ void k_geglu(const float* __restrict__ h, float* __restrict__ out, int M, int F) {
    int i = blockIdx.x * 256 + threadIdx.x;
    if (i >= M * F) return;
    int r = i / F, c = i - r * F;
    float a = h[r * 2 * F + c];
    float g = h[r * 2 * F + F + c];
    out[i] = a * 0.5f * g * (1.f + erff(g * 0.70710678118654752f));
}

__global__ void k_copy(const float* __restrict__ in, float* __restrict__ out, int n) {
    int i = blockIdx.x * 256 + threadIdx.x;
    if (i < n) out[i] = in[i];
}

// ---------------- driver ----------------
extern "C" void kernel_launch(void* const* d_in, const int* in_sizes, int n_in,
                              void* d_out, int out_size) {
    const float* x       = (const float*)d_in[0];
    const float* x_cont  = (const float*)d_in[1];
    const float* c_ln1_g = (const float*)d_in[2];
    const float* c_ln1_b = (const float*)d_in[3];
    const float* c_wqkv  = (const float*)d_in[4];
    const float* c_wo_w  = (const float*)d_in[5];
    const float* c_wo_b  = (const float*)d_in[6];
    const float* c_ln2_g = (const float*)d_in[7];
    const float* c_ln2_b = (const float*)d_in[8];
    const float* c_w1    = (const float*)d_in[9];
    const float* c_b1    = (const float*)d_in[10];
    const float* c_w2    = (const float*)d_in[11];
    const float* c_b2    = (const float*)d_in[12];
    const float* r_ln1_g = (const float*)d_in[13];
    const float* r_ln1_b = (const float*)d_in[14];
    const float* r_wqkv  = (const float*)d_in[15];
    const float* r_wo_w  = (const float*)d_in[16];
    const float* r_wo_b  = (const float*)d_in[17];
    const float* r_ln2_g = (const float*)d_in[18];
    const float* r_ln2_b = (const float*)d_in[19];
    const float* r_w1    = (const float*)d_in[20];
    const float* r_b1    = (const float*)d_in[21];
    const float* r_w2    = (const float*)d_in[22];
    const float* r_b2    = (const float*)d_in[23];

    float *px, *pxn, *pqkv, *pat, *ph, *pg;
    cudaGetSymbolAddress((void**)&px,   g_x);
    cudaGetSymbolAddress((void**)&pxn,  g_xn);
    cudaGetSymbolAddress((void**)&pqkv, g_qkv);
    cudaGetSymbolAddress((void**)&pat,  g_at);
    cudaGetSymbolAddress((void**)&ph,   g_h);
    cudaGetSymbolAddress((void**)&pg,   g_g);

    k_concat<<<(TOK * DIMM) / 256, 256>>>(x, x_cont, px);

    for (int L = 0; L < DEPTH; L++) {
        // ----- col block -----
        k_ln64<<<TOK / 8, 256>>>(px, c_ln1_g + L * 64, c_ln1_b + L * 64, pxn);
        k_gemm_mma<128><<<dim3(1536 / 128, TOK / 128), 256>>>(
            pxn, c_wqkv + L * 64 * 1536, nullptr, nullptr, pqkv, TOK, 1536, 64);
        k_colattn<<<dim3(BSAMP, HEADS), 256>>>(pqkv, pat);
        k_gemm_mma<64><<<dim3(1, TOK / 128), 256>>>(
            pat, c_wo_w + L * 512 * 64, c_wo_b + L * 64, pxn, px, TOK, 64, 512);
        k_ln64<<<TOK / 8, 256>>>(px, c_ln2_g + L * 64, c_ln2_b + L * 64, pxn);
        k_gemm_mma<128><<<dim3(512 / 128, TOK / 128), 256>>>(
            pxn, c_w1 + L * 64 * 512, c_b1 + L * 512, nullptr, ph, TOK, 512, 64);
        k_geglu<<<(TOK * DICOL) / 256, 256>>>(ph, pg, TOK, DICOL);
        k_gemm_mma<64><<<dim3(1, TOK / 128), 256>>>(
            pg, c_w2 + L * 256 * 64, c_b2 + L * 64, pxn, px, TOK, 64, 256);

        // ----- row block (x viewed as [2048, 2048], identical memory layout) -----
        k_ln2048<<<BSAMP, 256>>>(px, r_ln1_g + L * 2048, r_ln1_b + L * 2048, pxn);
        k_gemm_mma<128><<<dim3(1536 / 128, BSAMP / 128), 256>>>(
            pxn, r_wqkv + (size_t)L * 2048 * 1536, nullptr, nullptr, pqkv, BSAMP, 1536, 2048);
        k_rowattn<<<dim3(BSAMP / 32, HEADS), 256>>>(pqkv, pat);
        k_gemm_mma<128><<<dim3(2048 / 128, BSAMP / 128), 256>>>(
            pat, r_wo_w + (size_t)L * 512 * 2048, r_wo_b + L * 2048, pxn, px, BSAMP, 2048, 512);
        k_ln2048<<<BSAMP, 256>>>(px, r_ln2_g + L * 2048, r_ln2_b + L * 2048, pxn);
        k_gemm_mma<128><<<dim3(2048 / 128, BSAMP / 128), 256>>>(
            pxn, r_w1 + (size_t)L * 2048 * 2048, r_b1 + L * 2048, nullptr, ph, BSAMP, 2048, 2048);
        k_geglu<<<(BSAMP * DIROW) / 256, 256>>>(ph, pg, BSAMP, DIROW);
        k_gemm_mma<128><<<dim3(2048 / 128, BSAMP / 128), 256>>>(
            pg, r_w2 + (size_t)L * 1024 * 2048, r_b2 + L * 2048, pxn, px, BSAMP, 2048, 1024);
    }

    k_copy<<<(TOK * DIMM) / 256, 256>>>(px, (float*)d_out, TOK * DIMM);
}

// round 8
// speedup vs baseline: 1.7696x; 1.0810x over previous
#include <cuda_runtime.h>
#include <math.h>
#include <stdint.h>

#define TOK   65536      // B * NFEATS
#define BSAMP 2048
#define NF    32
#define DIMM  64
#define HEADS 8
#define DH    64
#define INNER 512
#define DROW  2048
#define DICOL 256
#define DIROW 1024
#define DEPTH 4
#define LN_EPS 1e-5f
#define KTILES (BSAMP / 64)   // 32 key tiles of 64 keys each

// round fp32 -> tf32 (matches tensor-core operand quantization)
__device__ __forceinline__ float tf32(float x) {
    uint32_t u;
    asm("cvt.rna.tf32.f32 %0, %1;" : "=r"(u) : "f"(x));
    return __uint_as_float(u);
}
__device__ __forceinline__ uint32_t tf32u(float x) {
    uint32_t u;
    asm("cvt.rna.tf32.f32 %0, %1;" : "=r"(u) : "f"(x));
    return u;
}

// m16n8k8 TF32 tensor-core mma (A row-major, B col-major, fp32 accum)
__device__ __forceinline__ void mma_tf32(float* c, const uint32_t* a, const uint32_t* b) {
    asm volatile(
        "mma.sync.aligned.m16n8k8.row.col.f32.tf32.tf32.f32 "
        "{%0,%1,%2,%3}, {%4,%5,%6,%7}, {%8,%9}, {%0,%1,%2,%3};"
        : "+f"(c[0]), "+f"(c[1]), "+f"(c[2]), "+f"(c[3])
        : "r"(a[0]), "r"(a[1]), "r"(a[2]), "r"(a[3]), "r"(b[0]), "r"(b[1]));
}

// cp.async helpers
__device__ __forceinline__ void cp_async16(uint32_t saddr, const void* gptr) {
    asm volatile("cp.async.cg.shared.global [%0], [%1], 16;" :: "r"(saddr), "l"(gptr));
}
__device__ __forceinline__ void cp_commit() { asm volatile("cp.async.commit_group;"); }
template<int N> __device__ __forceinline__ void cp_wait() {
    asm volatile("cp.async.wait_group %0;" :: "n"(N));
}
__device__ __forceinline__ uint32_t smem_u32(const void* p) {
    return (uint32_t)__cvta_generic_to_shared(p);
}

// ---------------- static scratch (no allocations allowed) ----------------
__device__ float g_x  [TOK * DIMM];
__device__ float g_xn [TOK * DIMM];
__device__ float g_qkv[TOK * 3 * INNER];
__device__ float g_at [TOK * INNER];
__device__ float g_h  [TOK * 2 * DICOL];
__device__ float g_g  [TOK * DICOL];

// ---------------- concat x / x_cont -> [B, 32, 64] ----------------
__global__ void k_concat(const float* __restrict__ x, const float* __restrict__ xc,
                         float* __restrict__ out) {
    int i = blockIdx.x * 256 + threadIdx.x;
    if (i >= TOK * DIMM) return;
    int d = i & 63;
    int t = i >> 6;
    int f = t & 31;
    int s = t >> 5;
    float v = (f < 16) ? x[(s * 16 + f) * 64 + d] : xc[(s * 16 + (f - 16)) * 64 + d];
    out[i] = v;
}

// ---------------- LayerNorm width 64 (warp per row) ----------------
__global__ void k_ln64(const float* __restrict__ in, const float* __restrict__ g,
                       const float* __restrict__ b, float* __restrict__ out) {
    int warp = (blockIdx.x * blockDim.x + threadIdx.x) >> 5;
    int lane = threadIdx.x & 31;
    if (warp >= TOK) return;
    const float* r = in + warp * 64;
    float v0 = r[lane], v1 = r[lane + 32];
    float s = v0 + v1;
    #pragma unroll
    for (int o = 16; o; o >>= 1) s += __shfl_xor_sync(0xffffffffu, s, o);
    float m = s * (1.f / 64.f);
    float d0 = v0 - m, d1 = v1 - m;
    float q = d0 * d0 + d1 * d1;
    #pragma unroll
    for (int o = 16; o; o >>= 1) q += __shfl_xor_sync(0xffffffffu, q, o);
    float inv = rsqrtf(q * (1.f / 64.f) + LN_EPS);
    float* w = out + warp * 64;
    w[lane]      = d0 * inv * g[lane]      + b[lane];
    w[lane + 32] = d1 * inv * g[lane + 32] + b[lane + 32];
}

// ---------------- LayerNorm width 2048 (block per row) ----------------
__global__ void k_ln2048(const float* __restrict__ in, const float* __restrict__ g,
                         const float* __restrict__ b, float* __restrict__ out) {
    int row = blockIdx.x;
    const float* r = in + row * 2048;
    float local[8];
    float s = 0.f;
    #pragma unroll
    for (int i = 0; i < 8; i++) { local[i] = r[threadIdx.x + i * 256]; s += local[i]; }
    __shared__ float red[256];
    red[threadIdx.x] = s; __syncthreads();
    for (int o = 128; o; o >>= 1) { if (threadIdx.x < o) red[threadIdx.x] += red[threadIdx.x + o]; __syncthreads(); }
    float m = red[0] * (1.f / 2048.f);
    __syncthreads();
    float q = 0.f;
    #pragma unroll
    for (int i = 0; i < 8; i++) { float d = local[i] - m; q += d * d; }
    red[threadIdx.x] = q; __syncthreads();
    for (int o = 128; o; o >>= 1) { if (threadIdx.x < o) red[threadIdx.x] += red[threadIdx.x + o]; __syncthreads(); }
    float inv = rsqrtf(red[0] * (1.f / 2048.f) + LN_EPS);
    #pragma unroll
    for (int i = 0; i < 8; i++) {
        int c = threadIdx.x + i * 256;
        out[row * 2048 + c] = (local[i] - m) * inv * g[c] + b[c];
    }
}

// ---------------- pipelined tensor-core TF32 GEMM ----------------
// C = A[M,K] @ W[K,N] (+bias)(+res). BM=128, BK=16, double-buffered cp.async.
// BN in {128, 64}. requires M%128==0, N%BN==0, K%16==0.
template<int BN>
__global__ void __launch_bounds__(256)
k_gemm_mma(const float* __restrict__ A, const float* __restrict__ W,
           const float* __restrict__ bias, const float* __restrict__ res,
           float* __restrict__ C, int M, int N, int K) {
    constexpr int BM = 128, BK = 16;
    constexpr int AST = BK + 4;                // A row stride 20: fragment loads conflict-free
    constexpr int BST = BN + 8;                // B row stride: conflict-free
    constexpr int WN = 32;
    constexpr int WM = (BN == 128) ? 64 : 32;
    constexpr int WARPS_N = BN / WN;
    constexpr int MT = WM / 16;
    constexpr int NT = WN / 8;
    __shared__ float As[2][BM][AST];
    __shared__ float Bs[2][BK][BST];

    int tid  = threadIdx.x;
    int warp = tid >> 5, lane = tid & 31;
    int gid  = lane >> 2, tg = lane & 3;
    int wm   = warp / WARPS_N, wn = warp % WARPS_N;
    int row0 = blockIdx.y * BM, col0 = blockIdx.x * BN;

    float acc[MT][NT][4];
    #pragma unroll
    for (int i = 0; i < MT; i++)
        #pragma unroll
        for (int j = 0; j < NT; j++)
            #pragma unroll
            for (int q = 0; q < 4; q++) acc[i][j][q] = 0.f;

    const int ntiles = K / BK;

    // async load of tile t into buffer buf
    auto load_tile = [&](int t, int buf) {
        int kt = t * BK;
        // A: 128 rows x 16k = 512 16B-chunks, 2 per thread
        #pragma unroll
        for (int i = 0; i < 2; i++) {
            int ch = tid + i * 256;
            int m = ch >> 2, kc = (ch & 3) * 4;
            cp_async16(smem_u32(&As[buf][m][kc]),
                       A + (size_t)(row0 + m) * K + kt + kc);
        }
        // B: 16 rows x BN = (BK*BN/4) chunks
        #pragma unroll
        for (int i = 0; i < (BK * BN) / (4 * 256); i++) {
            int ch = tid + i * 256;
            int k = ch / (BN / 4), nc = (ch % (BN / 4)) * 4;
            cp_async16(smem_u32(&Bs[buf][k][nc]),
                       W + (size_t)(kt + k) * N + col0 + nc);
        }
    };

    load_tile(0, 0);
    cp_commit();

    for (int t = 0; t < ntiles; t++) {
        int buf = t & 1;
        if (t + 1 < ntiles) {
            load_tile(t + 1, buf ^ 1);
            cp_commit();
            cp_wait<1>();
        } else {
            cp_wait<0>();
        }
        __syncthreads();

        #pragma unroll
        for (int ks = 0; ks < BK; ks += 8) {
            uint32_t af[MT][4], bf[NT][2];
            #pragma unroll
            for (int mt = 0; mt < MT; mt++) {
                int m0 = wm * WM + mt * 16;
                af[mt][0] = tf32u(As[buf][m0 + gid    ][ks + tg    ]);
                af[mt][1] = tf32u(As[buf][m0 + gid + 8][ks + tg    ]);
                af[mt][2] = tf32u(As[buf][m0 + gid    ][ks + tg + 4]);
                af[mt][3] = tf32u(As[buf][m0 + gid + 8][ks + tg + 4]);
            }
            #pragma unroll
            for (int nt = 0; nt < NT; nt++) {
                int n0 = wn * WN + nt * 8 + gid;
                bf[nt][0] = tf32u(Bs[buf][ks + tg    ][n0]);
                bf[nt][1] = tf32u(Bs[buf][ks + tg + 4][n0]);
            }
            #pragma unroll
            for (int mt = 0; mt < MT; mt++)
                #pragma unroll
                for (int nt = 0; nt < NT; nt++)
                    mma_tf32(acc[mt][nt], af[mt], bf[nt]);
        }
        __syncthreads();
    }

    #pragma unroll
    for (int mt = 0; mt < MT; mt++) {
        #pragma unroll
        for (int nt = 0; nt < NT; nt++) {
            int r0 = row0 + wm * WM + mt * 16 + gid;
            int c  = col0 + wn * WN + nt * 8 + tg * 2;
            float v0 = acc[mt][nt][0], v1 = acc[mt][nt][1];
            float v2 = acc[mt][nt][2], v3 = acc[mt][nt][3];
            if (bias) {
                float b0 = bias[c], b1 = bias[c + 1];
                v0 += b0; v1 += b1; v2 += b0; v3 += b1;
            }
            if (res) {
                v0 += res[(size_t)r0 * N + c];
                v1 += res[(size_t)r0 * N + c + 1];
                v2 += res[(size_t)(r0 + 8) * N + c];
                v3 += res[(size_t)(r0 + 8) * N + c + 1];
            }
            C[(size_t)r0 * N + c]           = v0;
            C[(size_t)r0 * N + c + 1]       = v1;
            C[(size_t)(r0 + 8) * N + c]     = v2;
            C[(size_t)(r0 + 8) * N + c + 1] = v3;
        }
    }
}

// ---------------- col attention: CTA per (sample, head), full softmax 32x32 ----------------
__global__ void k_colattn(const float* __restrict__ qkv, float* __restrict__ out) {
    int s = blockIdx.x, h = blockIdx.y;
    __shared__ float q[32][64], k[32][65], v[32][64], p[32][32];
    int tid = threadIdx.x;
    #pragma unroll
    for (int i = 0; i < 8; i++) {
        int idx = tid + i * 256;
        int r = idx >> 6, d = idx & 63;
        int base = (s * 32 + r) * 1536 + h * 64 + d;
        q[r][d] = tf32(qkv[base]);
        k[r][d] = tf32(qkv[base + 512]);
        v[r][d] = tf32(qkv[base + 1024]);
    }
    __syncthreads();
    #pragma unroll
    for (int i = 0; i < 4; i++) {
        int idx = tid + i * 256;
        int r = idx >> 5, c = idx & 31;
        float acc = 0.f;
        #pragma unroll
        for (int d = 0; d < 64; d++) acc += q[r][d] * k[c][d];
        p[r][c] = acc * 0.125f;
    }
    __syncthreads();
    int lane = tid & 31, w = tid >> 5;
    #pragma unroll
    for (int rr = 0; rr < 4; rr++) {
        int r = w * 4 + rr;
        float x = p[r][lane];
        float mx = x;
        #pragma unroll
        for (int o = 16; o; o >>= 1) mx = fmaxf(mx, __shfl_xor_sync(0xffffffffu, mx, o));
        float e = expf(x - mx);
        float sm = e;
        #pragma unroll
        for (int o = 16; o; o >>= 1) sm += __shfl_xor_sync(0xffffffffu, sm, o);
        p[r][lane] = tf32(e / sm);
    }
    __syncthreads();
    #pragma unroll
    for (int i = 0; i < 8; i++) {
        int idx = tid + i * 256;
        int r = idx >> 6, d = idx & 63;
        float acc = 0.f;
        #pragma unroll
        for (int j = 0; j < 32; j++) acc += p[r][j] * v[j][d];
        out[(s * 32 + r) * 512 + h * 64 + d] = acc;
    }
}

// ---------------- row attention: two-pass, CTA per (32-query tile, head) ----------------
__global__ void k_rowattn(const float* __restrict__ qkv, float* __restrict__ out) {
    int qb = blockIdx.x, h = blockIdx.y;
    __shared__ float qs[32][65];
    __shared__ float ks[64][65];
    __shared__ float vs[64][65];
    int tid = threadIdx.x;
    int row = tid >> 3;
    int cg  = tid & 7;
    #pragma unroll
    for (int i = 0; i < 8; i++) {
        int idx = tid + i * 256;
        int r = idx >> 6, d = idx & 63;
        qs[r][d] = tf32(qkv[(qb * 32 + r) * 1536 + h * 64 + d]);
    }
    __syncthreads();

    // ---------- pass 1: m, l ----------
    float m = -1e30f, l = 0.f;
    for (int kt = 0; kt < KTILES; kt++) {
        #pragma unroll
        for (int i = 0; i < 16; i++) {
            int idx = tid + i * 256;
            int r = idx >> 6, d = idx & 63;
            ks[r][d] = tf32(qkv[(kt * 64 + r) * 1536 + 512 + h * 64 + d]);
        }
        __syncthreads();
        float sv[8];
        float mx = m;
        #pragma unroll
        for (int jj = 0; jj < 8; jj++) {
            int j = cg * 8 + jj;
            float acc = 0.f;
            #pragma unroll
            for (int d = 0; d < 64; d++) acc += qs[row][d] * ks[j][d];
            acc *= 0.125f;
            sv[jj] = acc;
            mx = fmaxf(mx, acc);
        }
        #pragma unroll
        for (int o2 = 1; o2 < 8; o2 <<= 1) mx = fmaxf(mx, __shfl_xor_sync(0xffffffffu, mx, o2));
        float f = expf(m - mx);
        m = mx;
        float ps = 0.f;
        #pragma unroll
        for (int jj = 0; jj < 8; jj++) ps += expf(sv[jj] - mx);
        #pragma unroll
        for (int o2 = 1; o2 < 8; o2 <<= 1) ps += __shfl_xor_sync(0xffffffffu, ps, o2);
        l = l * f + ps;
        __syncthreads();
    }

    // ---------- pass 2: o = sum tf32(softmax) * v ----------
    float o[8] = {0, 0, 0, 0, 0, 0, 0, 0};
    for (int kt = 0; kt < KTILES; kt++) {
        #pragma unroll
        for (int i = 0; i < 16; i++) {
            int idx = tid + i * 256;
            int r = idx >> 6, d = idx & 63;
            int base = (kt * 64 + r) * 1536 + h * 64 + d;
            ks[r][d] = tf32(qkv[base + 512]);
            vs[r][d] = tf32(qkv[base + 1024]);
        }
        __syncthreads();
        float pv[8];
        #pragma unroll
        for (int jj = 0; jj < 8; jj++) {
            int j = cg * 8 + jj;
            float acc = 0.f;
            #pragma unroll
            for (int d = 0; d < 64; d++) acc += qs[row][d] * ks[j][d];
            acc *= 0.125f;
            pv[jj] = tf32(expf(acc - m) / l);
        }
        __syncthreads();
        #pragma unroll
        for (int jj = 0; jj < 8; jj++) ks[row][cg * 8 + jj] = pv[jj];
        __syncthreads();
        #pragma unroll
        for (int j = 0; j < 64; j++) {
            float pj = ks[row][j];
            #pragma unroll
            for (int dd = 0; dd < 8; dd++) o[dd] += pj * vs[j][cg * 8 + dd];
        }
        __syncthreads();
    }
    #pragma unroll
    for (int dd = 0; dd < 8; dd++)
        out[(qb * 32 + row) * 512 + h * 64 + cg * 8 + dd] = o[dd];
}

// ---------------- GEGLU: out = a * gelu_exact(g) ----------------
__global__ void k_geglu(const float* __restrict__ h, float* __restrict__ out, int M, int F) {
    int i = blockIdx.x * 256 + threadIdx.x;
    if (i >= M * F) return;
    int r = i / F, c = i - r * F;
    float a = h[r * 2 * F + c];
    float g = h[r * 2 * F + F + c];
    out[i] = a * 0.5f * g * (1.f + erff(g * 0.70710678118654752f));
}

__global__ void k_copy(const float* __restrict__ in, float* __restrict__ out, int n) {
    int i = blockIdx.x * 256 + threadIdx.x;
    if (i < n) out[i] = in[i];
}

// ---------------- driver ----------------
extern "C" void kernel_launch(void* const* d_in, const int* in_sizes, int n_in,
                              void* d_out, int out_size) {
    const float* x       = (const float*)d_in[0];
    const float* x_cont  = (const float*)d_in[1];
    const float* c_ln1_g = (const float*)d_in[2];
    const float* c_ln1_b = (const float*)d_in[3];
    const float* c_wqkv  = (const float*)d_in[4];
    const float* c_wo_w  = (const float*)d_in[5];
    const float* c_wo_b  = (const float*)d_in[6];
    const float* c_ln2_g = (const float*)d_in[7];
    const float* c_ln2_b = (const float*)d_in[8];
    const float* c_w1    = (const float*)d_in[9];
    const float* c_b1    = (const float*)d_in[10];
    const float* c_w2    = (const float*)d_in[11];
    const float* c_b2    = (const float*)d_in[12];
    const float* r_ln1_g = (const float*)d_in[13];
    const float* r_ln1_b = (const float*)d_in[14];
    const float* r_wqkv  = (const float*)d_in[15];
    const float* r_wo_w  = (const float*)d_in[16];
    const float* r_wo_b  = (const float*)d_in[17];
    const float* r_ln2_g = (const float*)d_in[18];
    const float* r_ln2_b = (const float*)d_in[19];
    const float* r_w1    = (const float*)d_in[20];
    const float* r_b1    = (const float*)d_in[21];
    const float* r_w2    = (const float*)d_in[22];
    const float* r_b2    = (const float*)d_in[23];

    float *px, *pxn, *pqkv, *pat, *ph, *pg;
    cudaGetSymbolAddress((void**)&px,   g_x);
    cudaGetSymbolAddress((void**)&pxn,  g_xn);
    cudaGetSymbolAddress((void**)&pqkv, g_qkv);
    cudaGetSymbolAddress((void**)&pat,  g_at);
    cudaGetSymbolAddress((void**)&ph,   g_h);
    cudaGetSymbolAddress((void**)&pg,   g_g);

    k_concat<<<(TOK * DIMM) / 256, 256>>>(x, x_cont, px);

    for (int L = 0; L < DEPTH; L++) {
        // ----- col block -----
        k_ln64<<<TOK / 8, 256>>>(px, c_ln1_g + L * 64, c_ln1_b + L * 64, pxn);
        k_gemm_mma<128><<<dim3(1536 / 128, TOK / 128), 256>>>(
            pxn, c_wqkv + L * 64 * 1536, nullptr, nullptr, pqkv, TOK, 1536, 64);
        k_colattn<<<dim3(BSAMP, HEADS), 256>>>(pqkv, pat);
        k_gemm_mma<64><<<dim3(1, TOK / 128), 256>>>(
            pat, c_wo_w + L * 512 * 64, c_wo_b + L * 64, pxn, px, TOK, 64, 512);
        k_ln64<<<TOK / 8, 256>>>(px, c_ln2_g + L * 64, c_ln2_b + L * 64, pxn);
        k_gemm_mma<128><<<dim3(512 / 128, TOK / 128), 256>>>(
            pxn, c_w1 + L * 64 * 512, c_b1 + L * 512, nullptr, ph, TOK, 512, 64);
        k_geglu<<<(TOK * DICOL) / 256, 256>>>(ph, pg, TOK, DICOL);
        k_gemm_mma<64><<<dim3(1, TOK / 128), 256>>>(
            pg, c_w2 + L * 256 * 64, c_b2 + L * 64, pxn, px, TOK, 64, 256);

        // ----- row block (x viewed as [2048, 2048], identical memory layout) -----
        k_ln2048<<<BSAMP, 256>>>(px, r_ln1_g + L * 2048, r_ln1_b + L * 2048, pxn);
        k_gemm_mma<128><<<dim3(1536 / 128, BSAMP / 128), 256>>>(
            pxn, r_wqkv + (size_t)L * 2048 * 1536, nullptr, nullptr, pqkv, BSAMP, 1536, 2048);
        k_rowattn<<<dim3(BSAMP / 32, HEADS), 256>>>(pqkv, pat);
        k_gemm_mma<128><<<dim3(2048 / 128, BSAMP / 128), 256>>>(
            pat, r_wo_w + (size_t)L * 512 * 2048, r_wo_b + L * 2048, pxn, px, BSAMP, 2048, 512);
        k_ln2048<<<BSAMP, 256>>>(px, r_ln2_g + L * 2048, r_ln2_b + L * 2048, pxn);
        k_gemm_mma<128><<<dim3(2048 / 128, BSAMP / 128), 256>>>(
            pxn, r_w1 + (size_t)L * 2048 * 2048, r_b1 + L * 2048, nullptr, ph, BSAMP, 2048, 2048);
        k_geglu<<<(BSAMP * DIROW) / 256, 256>>>(ph, pg, BSAMP, DIROW);
        k_gemm_mma<128><<<dim3(2048 / 128, BSAMP / 128), 256>>>(
            pg, r_w2 + (size_t)L * 1024 * 2048, r_b2 + L * 2048, pxn, px, BSAMP, 2048, 1024);
    }

    k_copy<<<(TOK * DIMM) / 256, 256>>>(px, (float*)d_out, TOK * DIMM);
}